// round 1
// baseline (speedup 1.0000x reference)
#include <cuda_runtime.h>
#include <cstdint>

#define N_EXPERTS 16
#define D_MODEL   1024
#define D_FF      2816
#define N_TOKENS  8192
#define TOP_K     2
#define A_TOTAL   (N_TOKENS * TOP_K)          // 16384 assignments

#define BM 128
#define BK 16
#define BN 64
#define AS_ST (BM + 8)    // 136: fragment loads bank = (8t+g)%32 -> conflict-free
#define BS_ST (BN + 8)    // 72 : fragment loads bank = (8t+g)%32 -> conflict-free

#define MAX_SLOTS  (A_TOTAL + N_EXPERTS * BM)  // 18432 (each expert padded to 128)
#define MAX_MTILES (MAX_SLOTS / BM)            // 144

// ---------------- scratch (device globals: no runtime allocation) ----------------
__device__ int   g_perm[MAX_SLOTS];
__device__ float g_wgt[MAX_SLOTS];
__device__ int   g_counts[N_EXPERTS];
__device__ int   g_offsets[N_EXPERTS];
__device__ int   g_tile_expert[MAX_MTILES];
__device__ float g_H[(size_t)MAX_SLOTS * D_FF];   // ~207 MB SwiGLU activations

// ---------------- helpers ----------------
__device__ __forceinline__ uint32_t f2tf(float f) {
    uint32_t r;
    asm("cvt.rna.tf32.f32 %0, %1;" : "=r"(r) : "f"(f));
    return r;
}

__device__ __forceinline__ void mma8(float* c, const uint32_t* a, const uint32_t* b) {
    asm volatile(
        "mma.sync.aligned.m16n8k8.row.col.f32.tf32.tf32.f32 "
        "{%0,%1,%2,%3}, {%4,%5,%6,%7}, {%8,%9}, {%0,%1,%2,%3};\n"
        : "+f"(c[0]), "+f"(c[1]), "+f"(c[2]), "+f"(c[3])
        : "r"(a[0]), "r"(a[1]), "r"(a[2]), "r"(a[3]),
          "r"(b[0]), "r"(b[1]));
}

__device__ __forceinline__ float silu_f(float x) {
    return x / (1.0f + __expf(-x));
}

// ---------------- dispatch ----------------
__global__ void init_kernel() {
    int i = blockIdx.x * blockDim.x + threadIdx.x;
    if (i < MAX_SLOTS) g_perm[i] = -1;
    if (i < N_EXPERTS) g_counts[i] = 0;
}

__global__ void zero_out_kernel(float4* __restrict__ out) {
    int i = blockIdx.x * blockDim.x + threadIdx.x;
    if (i < N_TOKENS * D_MODEL / 4) out[i] = make_float4(0.f, 0.f, 0.f, 0.f);
}

__global__ void count_kernel(const int* __restrict__ eidx) {
    int i = blockIdx.x * blockDim.x + threadIdx.x;
    if (i < A_TOTAL) atomicAdd(&g_counts[eidx[i]], 1);
}

__global__ void scan_kernel() {
    if (threadIdx.x == 0 && blockIdx.x == 0) {
        for (int i = 0; i < MAX_MTILES; i++) g_tile_expert[i] = -1;
        int acc = 0;
        for (int e = 0; e < N_EXPERTS; e++) {
            g_offsets[e] = acc;
            int nt = (g_counts[e] + BM - 1) / BM;
            int t0 = acc / BM;
            for (int i = 0; i < nt; i++) g_tile_expert[t0 + i] = e;
            acc += nt * BM;
        }
    }
}

__global__ void scatter_kernel(const int* __restrict__ eidx,
                               const float* __restrict__ ew) {
    int i = blockIdx.x * blockDim.x + threadIdx.x;
    if (i < A_TOTAL) {
        int e = eidx[i];
        int p = atomicAdd(&g_offsets[e], 1);
        g_perm[p] = i / TOP_K;
        g_wgt[p]  = ew[i];
    }
}

// ---------------- GEMM1: H = silu(X@W1) * (X@W2), gathered, per expert ----------------
// grid: (MAX_MTILES, D_FF/BN), 256 threads, block tile 128x64, warp tile 32x32
__global__ void __launch_bounds__(256)
gemm1_kernel(const float* __restrict__ x,
             const float* __restrict__ w1,
             const float* __restrict__ w2) {
    const int mt = blockIdx.x;
    const int e  = g_tile_expert[mt];
    if (e < 0) return;
    const int nb   = blockIdx.y * BN;
    const int row0 = mt * BM;

    __shared__ uint32_t As [2][BK][AS_ST];
    __shared__ uint32_t B1s[2][BK][BS_ST];
    __shared__ uint32_t B2s[2][BK][BS_ST];

    const int tid  = threadIdx.x;
    const int lane = tid & 31;
    const int wid  = tid >> 5;
    const int wm   = wid & 3;      // warp row tile (x32)
    const int wn   = wid >> 2;     // warp col tile (x32)
    const int g    = lane >> 2;
    const int t    = lane & 3;

    // A-load mapping: quantum q in [0,512): m = (q>>7)*32 + (q&31), kv = ((q>>5)&3)*4
    // -> within a warp, m spans 32 consecutive values: conflict-free STS
    const int q0 = tid, q1 = tid + 256;
    const int m0 = ((q0 >> 7) << 5) | (q0 & 31);
    const int m1 = ((q1 >> 7) << 5) | (q1 & 31);
    const int kv0 = ((q0 >> 5) & 3) << 2;
    const int kv1 = ((q1 >> 5) & 3) << 2;
    const int tok0 = g_perm[row0 + m0];
    const int tok1 = g_perm[row0 + m1];
    const float* ap0 = (tok0 >= 0) ? (x + (size_t)tok0 * D_MODEL + kv0) : nullptr;
    const float* ap1 = (tok1 >= 0) ? (x + (size_t)tok1 * D_MODEL + kv1) : nullptr;

    const int kB  = tid >> 4;            // [0,16)
    const int nvB = (tid & 15) << 2;     // [0,64) step 4
    const float* bp1 = w1 + (size_t)e * D_MODEL * D_FF + (size_t)kB * D_FF + nb + nvB;
    const float* bp2 = w2 + (size_t)e * D_MODEL * D_FF + (size_t)kB * D_FF + nb + nvB;

    float accg[2][4][4] = {};
    float accv[2][4][4] = {};

    float4 rA0, rA1, rB1, rB2;
    const float4 z4 = make_float4(0.f, 0.f, 0.f, 0.f);

    auto ldg_stage = [&](int kt) {
        int k0 = kt * BK;
        rA0 = ap0 ? *(const float4*)(ap0 + k0) : z4;
        rA1 = ap1 ? *(const float4*)(ap1 + k0) : z4;
        rB1 = *(const float4*)(bp1 + (size_t)k0 * D_FF);
        rB2 = *(const float4*)(bp2 + (size_t)k0 * D_FF);
    };
    auto sts_stage = [&](int s) {
        As[s][kv0 + 0][m0] = f2tf(rA0.x);
        As[s][kv0 + 1][m0] = f2tf(rA0.y);
        As[s][kv0 + 2][m0] = f2tf(rA0.z);
        As[s][kv0 + 3][m0] = f2tf(rA0.w);
        As[s][kv1 + 0][m1] = f2tf(rA1.x);
        As[s][kv1 + 1][m1] = f2tf(rA1.y);
        As[s][kv1 + 2][m1] = f2tf(rA1.z);
        As[s][kv1 + 3][m1] = f2tf(rA1.w);
        uint4 u1; u1.x = f2tf(rB1.x); u1.y = f2tf(rB1.y); u1.z = f2tf(rB1.z); u1.w = f2tf(rB1.w);
        uint4 u2; u2.x = f2tf(rB2.x); u2.y = f2tf(rB2.y); u2.z = f2tf(rB2.z); u2.w = f2tf(rB2.w);
        *(uint4*)&B1s[s][kB][nvB] = u1;
        *(uint4*)&B2s[s][kB][nvB] = u2;
    };

    ldg_stage(0);
    sts_stage(0);
    __syncthreads();

    const int KT = D_MODEL / BK;   // 64
    for (int kt = 0; kt < KT; kt++) {
        int s = kt & 1;
        if (kt + 1 < KT) ldg_stage(kt + 1);

#pragma unroll
        for (int ks = 0; ks < 2; ks++) {
            const int kk = ks * 8;
            uint32_t a[2][4];
#pragma unroll
            for (int mi = 0; mi < 2; mi++) {
                const int mr = wm * 32 + mi * 16;
                a[mi][0] = As[s][kk + t    ][mr + g];
                a[mi][1] = As[s][kk + t    ][mr + g + 8];
                a[mi][2] = As[s][kk + t + 4][mr + g];
                a[mi][3] = As[s][kk + t + 4][mr + g + 8];
            }
            uint32_t b1[4][2], b2[4][2];
#pragma unroll
            for (int ni = 0; ni < 4; ni++) {
                const int nc = wn * 32 + ni * 8 + g;
                b1[ni][0] = B1s[s][kk + t    ][nc];
                b1[ni][1] = B1s[s][kk + t + 4][nc];
                b2[ni][0] = B2s[s][kk + t    ][nc];
                b2[ni][1] = B2s[s][kk + t + 4][nc];
            }
#pragma unroll
            for (int mi = 0; mi < 2; mi++)
#pragma unroll
                for (int ni = 0; ni < 4; ni++) {
                    mma8(accg[mi][ni], a[mi], b1[ni]);
                    mma8(accv[mi][ni], a[mi], b2[ni]);
                }
        }

        if (kt + 1 < KT) sts_stage((kt + 1) & 1);
        __syncthreads();
    }

    // epilogue: SwiGLU -> H  (pad rows are all-zero A -> writes 0, harmless)
#pragma unroll
    for (int mi = 0; mi < 2; mi++) {
        const int r = wm * 32 + mi * 16 + g;
        const size_t h0 = (size_t)(row0 + r)     * D_FF;
        const size_t h8 = (size_t)(row0 + r + 8) * D_FF;
#pragma unroll
        for (int ni = 0; ni < 4; ni++) {
            const int c = nb + wn * 32 + ni * 8 + 2 * t;
            g_H[h0 + c    ] = silu_f(accg[mi][ni][0]) * accv[mi][ni][0];
            g_H[h0 + c + 1] = silu_f(accg[mi][ni][1]) * accv[mi][ni][1];
            g_H[h8 + c    ] = silu_f(accg[mi][ni][2]) * accv[mi][ni][2];
            g_H[h8 + c + 1] = silu_f(accg[mi][ni][3]) * accv[mi][ni][3];
        }
    }
}

// ---------------- GEMM2: out[token] += wgt * (H @ W3) ----------------
// grid: (MAX_MTILES, D_MODEL/BN), 256 threads
__global__ void __launch_bounds__(256)
gemm2_kernel(const float* __restrict__ w3, float* __restrict__ out) {
    const int mt = blockIdx.x;
    const int e  = g_tile_expert[mt];
    if (e < 0) return;
    const int nb   = blockIdx.y * BN;
    const int row0 = mt * BM;

    __shared__ uint32_t As[2][BK][AS_ST];
    __shared__ uint32_t Bs[2][BK][BS_ST];

    const int tid  = threadIdx.x;
    const int lane = tid & 31;
    const int wid  = tid >> 5;
    const int wm   = wid & 3;
    const int wn   = wid >> 2;
    const int g    = lane >> 2;
    const int t    = lane & 3;

    const int q0 = tid, q1 = tid + 256;
    const int m0 = ((q0 >> 7) << 5) | (q0 & 31);
    const int m1 = ((q1 >> 7) << 5) | (q1 & 31);
    const int kv0 = ((q0 >> 5) & 3) << 2;
    const int kv1 = ((q1 >> 5) & 3) << 2;
    const float* ap0 = g_H + (size_t)(row0 + m0) * D_FF + kv0;
    const float* ap1 = g_H + (size_t)(row0 + m1) * D_FF + kv1;

    const int kB  = tid >> 4;
    const int nvB = (tid & 15) << 2;
    const float* bp = w3 + (size_t)e * D_FF * D_MODEL + (size_t)kB * D_MODEL + nb + nvB;

    float acc[2][4][4] = {};

    float4 rA0, rA1, rB;
    auto ldg_stage = [&](int kt) {
        int k0 = kt * BK;
        rA0 = *(const float4*)(ap0 + k0);
        rA1 = *(const float4*)(ap1 + k0);
        rB  = *(const float4*)(bp + (size_t)k0 * D_MODEL);
    };
    auto sts_stage = [&](int s) {
        As[s][kv0 + 0][m0] = f2tf(rA0.x);
        As[s][kv0 + 1][m0] = f2tf(rA0.y);
        As[s][kv0 + 2][m0] = f2tf(rA0.z);
        As[s][kv0 + 3][m0] = f2tf(rA0.w);
        As[s][kv1 + 0][m1] = f2tf(rA1.x);
        As[s][kv1 + 1][m1] = f2tf(rA1.y);
        As[s][kv1 + 2][m1] = f2tf(rA1.z);
        As[s][kv1 + 3][m1] = f2tf(rA1.w);
        uint4 u; u.x = f2tf(rB.x); u.y = f2tf(rB.y); u.z = f2tf(rB.z); u.w = f2tf(rB.w);
        *(uint4*)&Bs[s][kB][nvB] = u;
    };

    ldg_stage(0);
    sts_stage(0);
    __syncthreads();

    const int KT = D_FF / BK;   // 176
    for (int kt = 0; kt < KT; kt++) {
        int s = kt & 1;
        if (kt + 1 < KT) ldg_stage(kt + 1);

#pragma unroll
        for (int ks = 0; ks < 2; ks++) {
            const int kk = ks * 8;
            uint32_t a[2][4];
#pragma unroll
            for (int mi = 0; mi < 2; mi++) {
                const int mr = wm * 32 + mi * 16;
                a[mi][0] = As[s][kk + t    ][mr + g];
                a[mi][1] = As[s][kk + t    ][mr + g + 8];
                a[mi][2] = As[s][kk + t + 4][mr + g];
                a[mi][3] = As[s][kk + t + 4][mr + g + 8];
            }
            uint32_t b[4][2];
#pragma unroll
            for (int ni = 0; ni < 4; ni++) {
                const int nc = wn * 32 + ni * 8 + g;
                b[ni][0] = Bs[s][kk + t    ][nc];
                b[ni][1] = Bs[s][kk + t + 4][nc];
            }
#pragma unroll
            for (int mi = 0; mi < 2; mi++)
#pragma unroll
                for (int ni = 0; ni < 4; ni++)
                    mma8(acc[mi][ni], a[mi], b[ni]);
        }

        if (kt + 1 < KT) sts_stage((kt + 1) & 1);
        __syncthreads();
    }

    // epilogue: weighted scatter-add (exactly 2 contributions per token -> deterministic)
#pragma unroll
    for (int mi = 0; mi < 2; mi++) {
        const int r  = wm * 32 + mi * 16 + g;
        const int s0 = row0 + r;
        const int s8 = s0 + 8;
        const int tk0 = g_perm[s0];
        const int tk8 = g_perm[s8];
        const float wt0 = (tk0 >= 0) ? g_wgt[s0] : 0.f;
        const float wt8 = (tk8 >= 0) ? g_wgt[s8] : 0.f;
#pragma unroll
        for (int ni = 0; ni < 4; ni++) {
            const int c = nb + wn * 32 + ni * 8 + 2 * t;
            if (tk0 >= 0) {
                atomicAdd(&out[(size_t)tk0 * D_MODEL + c    ], acc[mi][ni][0] * wt0);
                atomicAdd(&out[(size_t)tk0 * D_MODEL + c + 1], acc[mi][ni][1] * wt0);
            }
            if (tk8 >= 0) {
                atomicAdd(&out[(size_t)tk8 * D_MODEL + c    ], acc[mi][ni][2] * wt8);
                atomicAdd(&out[(size_t)tk8 * D_MODEL + c + 1], acc[mi][ni][3] * wt8);
            }
        }
    }
}

// ---------------- launch ----------------
extern "C" void kernel_launch(void* const* d_in, const int* in_sizes, int n_in,
                              void* d_out, int out_size) {
    const float* x    = (const float*)d_in[0];
    const int*   eidx = (const int*)  d_in[1];
    const float* ew   = (const float*)d_in[2];
    const float* w1   = (const float*)d_in[3];
    const float* w2   = (const float*)d_in[4];
    const float* w3   = (const float*)d_in[5];
    float* out = (float*)d_out;

    init_kernel<<<(MAX_SLOTS + 255) / 256, 256>>>();
    zero_out_kernel<<<(N_TOKENS * D_MODEL / 4 + 255) / 256, 256>>>((float4*)out);
    count_kernel<<<(A_TOTAL + 255) / 256, 256>>>(eidx);
    scan_kernel<<<1, 32>>>();
    scatter_kernel<<<(A_TOTAL + 255) / 256, 256>>>(eidx, ew);

    gemm1_kernel<<<dim3(MAX_MTILES, D_FF / BN), 256>>>(x, w1, w2);
    gemm2_kernel<<<dim3(MAX_MTILES, D_MODEL / BN), 256>>>(w3, out);
}

// round 2
// speedup vs baseline: 1.5020x; 1.5020x over previous
#include <cuda_runtime.h>
#include <cstdint>

#define N_EXPERTS 16
#define D_MODEL   1024
#define D_FF      2816
#define N_TOKENS  8192
#define TOP_K     2
#define A_TOTAL   (N_TOKENS * TOP_K)

#define BM 128
#define BK 16
#define BN 128
#define STAGES 4

#define A_STRIDE 20      // (g*20+t) % 32 distinct for g in 0..7, t in 0..3
#define B_STRIDE 136     // 136 % 32 == 8 -> (t*8+g) % 32 distinct
#define A_STAGE (BM * A_STRIDE)   // 2560 floats
#define B_STAGE (BK * B_STRIDE)   // 2176 floats

#define MAX_SLOTS  (A_TOTAL + N_EXPERTS * BM)  // 18432
#define MAX_MTILES (MAX_SLOTS / BM)            // 144

// ---------------- scratch ----------------
__device__ int   g_perm[MAX_SLOTS];
__device__ float g_wgt[MAX_SLOTS];
__device__ int   g_counts[N_EXPERTS];
__device__ int   g_offsets[N_EXPERTS];
__device__ int   g_tile_expert[MAX_MTILES];
__device__ float g_H[(size_t)MAX_SLOTS * D_FF];   // ~207 MB

// ---------------- helpers ----------------
__device__ __forceinline__ uint32_t f2tf(float f) {
    uint32_t r;
    asm("cvt.rna.tf32.f32 %0, %1;" : "=r"(r) : "f"(f));
    return r;
}
__device__ __forceinline__ void mma8(float* c, const uint32_t* a, const uint32_t* b) {
    asm volatile(
        "mma.sync.aligned.m16n8k8.row.col.f32.tf32.tf32.f32 "
        "{%0,%1,%2,%3}, {%4,%5,%6,%7}, {%8,%9}, {%0,%1,%2,%3};\n"
        : "+f"(c[0]), "+f"(c[1]), "+f"(c[2]), "+f"(c[3])
        : "r"(a[0]), "r"(a[1]), "r"(a[2]), "r"(a[3]),
          "r"(b[0]), "r"(b[1]));
}
__device__ __forceinline__ float silu_f(float x) { return x / (1.0f + __expf(-x)); }

__device__ __forceinline__ uint32_t smem_u32(const void* p) {
    return (uint32_t)__cvta_generic_to_shared(p);
}
__device__ __forceinline__ void cp16(uint32_t dst, const void* src) {
    asm volatile("cp.async.cg.shared.global [%0], [%1], 16;" :: "r"(dst), "l"(src));
}
__device__ __forceinline__ void cp16_pred(uint32_t dst, const void* src, int valid) {
    int sz = valid ? 16 : 0;
    asm volatile("cp.async.cg.shared.global [%0], [%1], 16, %2;"
                 :: "r"(dst), "l"(src), "r"(sz));
}
#define CP_COMMIT() asm volatile("cp.async.commit_group;" ::: "memory")
#define CP_WAIT2()  asm volatile("cp.async.wait_group 2;"  ::: "memory")

// ---------------- dispatch ----------------
__global__ void init_kernel() {
    int i = blockIdx.x * blockDim.x + threadIdx.x;
    if (i < MAX_SLOTS) g_perm[i] = -1;
    if (i < N_EXPERTS) g_counts[i] = 0;
}
__global__ void zero_out_kernel(float4* __restrict__ out) {
    int i = blockIdx.x * blockDim.x + threadIdx.x;
    if (i < N_TOKENS * D_MODEL / 4) out[i] = make_float4(0.f, 0.f, 0.f, 0.f);
}
__global__ void count_kernel(const int* __restrict__ eidx) {
    int i = blockIdx.x * blockDim.x + threadIdx.x;
    if (i < A_TOTAL) atomicAdd(&g_counts[eidx[i]], 1);
}
__global__ void scan_kernel() {
    if (threadIdx.x == 0 && blockIdx.x == 0) {
        for (int i = 0; i < MAX_MTILES; i++) g_tile_expert[i] = -1;
        int acc = 0;
        for (int e = 0; e < N_EXPERTS; e++) {
            g_offsets[e] = acc;
            int nt = (g_counts[e] + BM - 1) / BM;
            int t0 = acc / BM;
            for (int i = 0; i < nt; i++) g_tile_expert[t0 + i] = e;
            acc += nt * BM;
        }
    }
}
__global__ void scatter_kernel(const int* __restrict__ eidx,
                               const float* __restrict__ ew) {
    int i = blockIdx.x * blockDim.x + threadIdx.x;
    if (i < A_TOTAL) {
        int e = eidx[i];
        int p = atomicAdd(&g_offsets[e], 1);
        g_perm[p] = i / TOP_K;
        g_wgt[p]  = ew[i];
    }
}

// ---------------- GEMM1: H = silu(X@W1) * (X@W2) ----------------
// grid (D_FF/BN, MAX_MTILES), 256 thr. Warps 4(m) x 2(n), warp tile 32x64.
__global__ void __launch_bounds__(256)
gemm1_kernel(const float* __restrict__ x,
             const float* __restrict__ w1,
             const float* __restrict__ w2) {
    const int mt = blockIdx.y;
    const int e  = g_tile_expert[mt];
    if (e < 0) return;
    const int nb   = blockIdx.x * BN;
    const int row0 = mt * BM;

    extern __shared__ float smem[];
    float* sA  = smem;                          // STAGES * A_STAGE
    float* sB1 = sA  + STAGES * A_STAGE;        // STAGES * B_STAGE
    float* sB2 = sB1 + STAGES * B_STAGE;

    const int tid  = threadIdx.x;
    const int lane = tid & 31;
    const int wid  = tid >> 5;
    const int wm   = wid & 3;
    const int wn   = wid >> 2;
    const int g    = lane >> 2;
    const int t    = lane & 3;

    // A loader: 2 tasks/thread, task j -> row m=j>>2, 16B quad kq=j&3
    const int mA0 = tid >> 2;            // [0,64)
    const int mA1 = mA0 + 64;            // [64,128)
    const int kqA = tid & 3;
    const int tok0 = g_perm[row0 + mA0];
    const int tok1 = g_perm[row0 + mA1];
    const float* apg0 = x + (size_t)(tok0 < 0 ? 0 : tok0) * D_MODEL + kqA * 4;
    const float* apg1 = x + (size_t)(tok1 < 0 ? 0 : tok1) * D_MODEL + kqA * 4;
    const int av0 = (tok0 >= 0), av1 = (tok1 >= 0);
    const uint32_t dA0 = smem_u32(sA + mA0 * A_STRIDE + kqA * 4);
    const uint32_t dA1 = smem_u32(sA + mA1 * A_STRIDE + kqA * 4);

    // B loader: 2 tasks/thread, task j -> row k=j>>5, quad nq=j&31
    const int kB0 = tid >> 5;            // [0,8)
    const int kB1 = kB0 + 8;             // [8,16)
    const int nqB = tid & 31;
    const float* bg1 = w1 + (size_t)e * D_MODEL * D_FF + nb + nqB * 4;
    const float* bg2 = w2 + (size_t)e * D_MODEL * D_FF + nb + nqB * 4;
    const uint32_t dB1a = smem_u32(sB1 + kB0 * B_STRIDE + nqB * 4);
    const uint32_t dB1b = smem_u32(sB1 + kB1 * B_STRIDE + nqB * 4);
    const uint32_t dB2a = smem_u32(sB2 + kB0 * B_STRIDE + nqB * 4);
    const uint32_t dB2b = smem_u32(sB2 + kB1 * B_STRIDE + nqB * 4);

    const int KT = D_MODEL / BK;   // 64

    auto issue = [&](int kt) {
        if (kt < KT) {
            const int s = kt & (STAGES - 1);
            const int kg = kt * BK;
            cp16_pred(dA0 + s * A_STAGE * 4, apg0 + kg, av0);
            cp16_pred(dA1 + s * A_STAGE * 4, apg1 + kg, av1);
            cp16(dB1a + s * B_STAGE * 4, bg1 + (size_t)(kg + kB0) * D_FF);
            cp16(dB1b + s * B_STAGE * 4, bg1 + (size_t)(kg + kB1) * D_FF);
            cp16(dB2a + s * B_STAGE * 4, bg2 + (size_t)(kg + kB0) * D_FF);
            cp16(dB2b + s * B_STAGE * 4, bg2 + (size_t)(kg + kB1) * D_FF);
        }
        CP_COMMIT();
    };

    float accg[2][8][4] = {};
    float accv[2][8][4] = {};

    issue(0); issue(1); issue(2);

    for (int kt = 0; kt < KT; kt++) {
        CP_WAIT2();
        __syncthreads();
        issue(kt + 3);

        const int s = kt & (STAGES - 1);
        const float* As  = sA  + s * A_STAGE;
        const float* B1s = sB1 + s * B_STAGE;
        const float* B2s = sB2 + s * B_STAGE;

#pragma unroll
        for (int ks = 0; ks < 2; ks++) {
            const int kk = ks * 8;
            uint32_t a[2][4];
#pragma unroll
            for (int mi = 0; mi < 2; mi++) {
                const int mr = wm * 32 + mi * 16;
                a[mi][0] = f2tf(As[(mr + g    ) * A_STRIDE + kk + t    ]);
                a[mi][1] = f2tf(As[(mr + g + 8) * A_STRIDE + kk + t    ]);
                a[mi][2] = f2tf(As[(mr + g    ) * A_STRIDE + kk + t + 4]);
                a[mi][3] = f2tf(As[(mr + g + 8) * A_STRIDE + kk + t + 4]);
            }
#pragma unroll
            for (int ni = 0; ni < 8; ni++) {
                const int nc = wn * 64 + ni * 8 + g;
                uint32_t b1[2], b2[2];
                b1[0] = f2tf(B1s[(kk + t    ) * B_STRIDE + nc]);
                b1[1] = f2tf(B1s[(kk + t + 4) * B_STRIDE + nc]);
                b2[0] = f2tf(B2s[(kk + t    ) * B_STRIDE + nc]);
                b2[1] = f2tf(B2s[(kk + t + 4) * B_STRIDE + nc]);
#pragma unroll
                for (int mi = 0; mi < 2; mi++) {
                    mma8(accg[mi][ni], a[mi], b1);
                    mma8(accv[mi][ni], a[mi], b2);
                }
            }
        }
        __syncthreads();
    }

    // epilogue: SwiGLU -> H
#pragma unroll
    for (int mi = 0; mi < 2; mi++) {
        const int r = wm * 32 + mi * 16 + g;
        const size_t h0 = (size_t)(row0 + r)     * D_FF;
        const size_t h8 = (size_t)(row0 + r + 8) * D_FF;
#pragma unroll
        for (int ni = 0; ni < 8; ni++) {
            const int c = nb + wn * 64 + ni * 8 + 2 * t;
            float2 v0, v8;
            v0.x = silu_f(accg[mi][ni][0]) * accv[mi][ni][0];
            v0.y = silu_f(accg[mi][ni][1]) * accv[mi][ni][1];
            v8.x = silu_f(accg[mi][ni][2]) * accv[mi][ni][2];
            v8.y = silu_f(accg[mi][ni][3]) * accv[mi][ni][3];
            *(float2*)&g_H[h0 + c] = v0;
            *(float2*)&g_H[h8 + c] = v8;
        }
    }
}

// ---------------- GEMM2: out += wgt * (H @ W3) ----------------
// grid (D_MODEL/BN, MAX_MTILES), 256 thr.
__global__ void __launch_bounds__(256)
gemm2_kernel(const float* __restrict__ w3, float* __restrict__ out) {
    const int mt = blockIdx.y;
    const int e  = g_tile_expert[mt];
    if (e < 0) return;
    const int nb   = blockIdx.x * BN;
    const int row0 = mt * BM;

    extern __shared__ float smem[];
    float* sA = smem;
    float* sB = sA + STAGES * A_STAGE;

    const int tid  = threadIdx.x;
    const int lane = tid & 31;
    const int wid  = tid >> 5;
    const int wm   = wid & 3;
    const int wn   = wid >> 2;
    const int g    = lane >> 2;
    const int t    = lane & 3;

    const int mA0 = tid >> 2;
    const int mA1 = mA0 + 64;
    const int kqA = tid & 3;
    const float* apg0 = g_H + (size_t)(row0 + mA0) * D_FF + kqA * 4;
    const float* apg1 = g_H + (size_t)(row0 + mA1) * D_FF + kqA * 4;
    const uint32_t dA0 = smem_u32(sA + mA0 * A_STRIDE + kqA * 4);
    const uint32_t dA1 = smem_u32(sA + mA1 * A_STRIDE + kqA * 4);

    const int kB0 = tid >> 5;
    const int kB1 = kB0 + 8;
    const int nqB = tid & 31;
    const float* bg = w3 + (size_t)e * D_FF * D_MODEL + nb + nqB * 4;
    const uint32_t dBa = smem_u32(sB + kB0 * B_STRIDE + nqB * 4);
    const uint32_t dBb = smem_u32(sB + kB1 * B_STRIDE + nqB * 4);

    const int KT = D_FF / BK;   // 176

    auto issue = [&](int kt) {
        if (kt < KT) {
            const int s = kt & (STAGES - 1);
            const int kg = kt * BK;
            cp16(dA0 + s * A_STAGE * 4, apg0 + kg);
            cp16(dA1 + s * A_STAGE * 4, apg1 + kg);
            cp16(dBa + s * B_STAGE * 4, bg + (size_t)(kg + kB0) * D_MODEL);
            cp16(dBb + s * B_STAGE * 4, bg + (size_t)(kg + kB1) * D_MODEL);
        }
        CP_COMMIT();
    };

    float acc[2][8][4] = {};

    issue(0); issue(1); issue(2);

    for (int kt = 0; kt < KT; kt++) {
        CP_WAIT2();
        __syncthreads();
        issue(kt + 3);

        const int s = kt & (STAGES - 1);
        const float* As = sA + s * A_STAGE;
        const float* Bs = sB + s * B_STAGE;

#pragma unroll
        for (int ks = 0; ks < 2; ks++) {
            const int kk = ks * 8;
            uint32_t a[2][4];
#pragma unroll
            for (int mi = 0; mi < 2; mi++) {
                const int mr = wm * 32 + mi * 16;
                a[mi][0] = f2tf(As[(mr + g    ) * A_STRIDE + kk + t    ]);
                a[mi][1] = f2tf(As[(mr + g + 8) * A_STRIDE + kk + t    ]);
                a[mi][2] = f2tf(As[(mr + g    ) * A_STRIDE + kk + t + 4]);
                a[mi][3] = f2tf(As[(mr + g + 8) * A_STRIDE + kk + t + 4]);
            }
#pragma unroll
            for (int ni = 0; ni < 8; ni++) {
                const int nc = wn * 64 + ni * 8 + g;
                uint32_t b[2];
                b[0] = f2tf(Bs[(kk + t    ) * B_STRIDE + nc]);
                b[1] = f2tf(Bs[(kk + t + 4) * B_STRIDE + nc]);
#pragma unroll
                for (int mi = 0; mi < 2; mi++)
                    mma8(acc[mi][ni], a[mi], b);
            }
        }
        __syncthreads();
    }

    // epilogue: weighted scatter-add
#pragma unroll
    for (int mi = 0; mi < 2; mi++) {
        const int r  = wm * 32 + mi * 16 + g;
        const int s0 = row0 + r;
        const int s8 = s0 + 8;
        const int tk0 = g_perm[s0];
        const int tk8 = g_perm[s8];
        const float wt0 = (tk0 >= 0) ? g_wgt[s0] : 0.f;
        const float wt8 = (tk8 >= 0) ? g_wgt[s8] : 0.f;
#pragma unroll
        for (int ni = 0; ni < 8; ni++) {
            const int c = nb + wn * 64 + ni * 8 + 2 * t;
            if (tk0 >= 0) {
                atomicAdd(&out[(size_t)tk0 * D_MODEL + c    ], acc[mi][ni][0] * wt0);
                atomicAdd(&out[(size_t)tk0 * D_MODEL + c + 1], acc[mi][ni][1] * wt0);
            }
            if (tk8 >= 0) {
                atomicAdd(&out[(size_t)tk8 * D_MODEL + c    ], acc[mi][ni][2] * wt8);
                atomicAdd(&out[(size_t)tk8 * D_MODEL + c + 1], acc[mi][ni][3] * wt8);
            }
        }
    }
}

// ---------------- launch ----------------
extern "C" void kernel_launch(void* const* d_in, const int* in_sizes, int n_in,
                              void* d_out, int out_size) {
    const float* x    = (const float*)d_in[0];
    const int*   eidx = (const int*)  d_in[1];
    const float* ew   = (const float*)d_in[2];
    const float* w1   = (const float*)d_in[3];
    const float* w2   = (const float*)d_in[4];
    const float* w3   = (const float*)d_in[5];
    float* out = (float*)d_out;

    const int smem1 = STAGES * (A_STAGE + 2 * B_STAGE) * 4;   // 110592 B
    const int smem2 = STAGES * (A_STAGE + B_STAGE) * 4;       //  75776 B
    static int attr_done = 0;
    if (!attr_done) {
        cudaFuncSetAttribute(gemm1_kernel, cudaFuncAttributeMaxDynamicSharedMemorySize, smem1);
        cudaFuncSetAttribute(gemm2_kernel, cudaFuncAttributeMaxDynamicSharedMemorySize, smem2);
        attr_done = 1;
    }

    init_kernel<<<(MAX_SLOTS + 255) / 256, 256>>>();
    zero_out_kernel<<<(N_TOKENS * D_MODEL / 4 + 255) / 256, 256>>>((float4*)out);
    count_kernel<<<(A_TOTAL + 255) / 256, 256>>>(eidx);
    scan_kernel<<<1, 32>>>();
    scatter_kernel<<<(A_TOTAL + 255) / 256, 256>>>(eidx, ew);

    gemm1_kernel<<<dim3(D_FF / BN, MAX_MTILES), 256, smem1>>>(x, w1, w2);
    gemm2_kernel<<<dim3(D_MODEL / BN, MAX_MTILES), 256, smem2>>>(w3, out);
}

// round 4
// speedup vs baseline: 1.8399x; 1.2249x over previous
#include <cuda_runtime.h>
#include <cstdint>

#define N_EXPERTS 16
#define D_MODEL   1024
#define D_FF      2816
#define N_TOKENS  8192
#define TOP_K     2
#define A_TOTAL   (N_TOKENS * TOP_K)

#define BM 128
#define BK 32
#define BN 128

#define A_STRIDE 36      // [m][k] row stride: bank (4g+t)%32 distinct -> conflict-free frags
#define B_STRIDE 136     // [k][n] row stride: bank (8t+g)%32 distinct -> conflict-free frags
#define A_STAGE (BM * A_STRIDE)   // 4608 floats
#define B_STAGE (BK * B_STRIDE)   // 4352 floats

#define MAX_SLOTS  (A_TOTAL + N_EXPERTS * BM)  // 18432
#define MAX_MTILES (MAX_SLOTS / BM)            // 144

// ---------------- scratch ----------------
__device__ int   g_perm[MAX_SLOTS];
__device__ float g_wgt[MAX_SLOTS];
__device__ int   g_counts[N_EXPERTS];
__device__ int   g_offsets[N_EXPERTS];
__device__ int   g_tile_expert[MAX_MTILES];
__device__ float g_Xr[(size_t)N_TOKENS * D_MODEL];   // tf32-pre-rounded x (32 MB)
__device__ float g_H[(size_t)MAX_SLOTS * D_FF];      // SwiGLU activations (~207 MB, tf32-rounded)

// ---------------- helpers ----------------
__device__ __forceinline__ uint32_t f2tf(float f) {
    uint32_t r;
    asm("cvt.rna.tf32.f32 %0, %1;" : "=r"(r) : "f"(f));
    return r;
}
__device__ __forceinline__ void mma8(float* c, const uint32_t* a, const uint32_t* b) {
    asm volatile(
        "mma.sync.aligned.m16n8k8.row.col.f32.tf32.tf32.f32 "
        "{%0,%1,%2,%3}, {%4,%5,%6,%7}, {%8,%9}, {%0,%1,%2,%3};\n"
        : "+f"(c[0]), "+f"(c[1]), "+f"(c[2]), "+f"(c[3])
        : "r"(a[0]), "r"(a[1]), "r"(a[2]), "r"(a[3]),
          "r"(b[0]), "r"(b[1]));
}
__device__ __forceinline__ float silu_f(float x) { return x / (1.0f + __expf(-x)); }
__device__ __forceinline__ uint32_t smem_u32(const void* p) {
    return (uint32_t)__cvta_generic_to_shared(p);
}
__device__ __forceinline__ void cp16(uint32_t dst, const void* src) {
    asm volatile("cp.async.cg.shared.global [%0], [%1], 16;" :: "r"(dst), "l"(src));
}
__device__ __forceinline__ void cp16_pred(uint32_t dst, const void* src, int valid) {
    int sz = valid ? 16 : 0;
    asm volatile("cp.async.cg.shared.global [%0], [%1], 16, %2;"
                 :: "r"(dst), "l"(src), "r"(sz));
}
#define CP_COMMIT() asm volatile("cp.async.commit_group;" ::: "memory")
#define CP_WAIT1()  asm volatile("cp.async.wait_group 1;"  ::: "memory")

// ---------------- dispatch ----------------
__global__ void init_kernel() {
    int i = blockIdx.x * blockDim.x + threadIdx.x;
    if (i < MAX_SLOTS) g_perm[i] = -1;
    if (i < N_EXPERTS) g_counts[i] = 0;
}
__global__ void zero_out_kernel(float4* __restrict__ out) {
    int i = blockIdx.x * blockDim.x + threadIdx.x;
    if (i < N_TOKENS * D_MODEL / 4) out[i] = make_float4(0.f, 0.f, 0.f, 0.f);
}
__global__ void round_x_kernel(const float4* __restrict__ x) {
    int i = blockIdx.x * blockDim.x + threadIdx.x;
    if (i < N_TOKENS * D_MODEL / 4) {
        float4 v = x[i];
        uint4 u;
        u.x = f2tf(v.x); u.y = f2tf(v.y); u.z = f2tf(v.z); u.w = f2tf(v.w);
        *(uint4*)&g_Xr[(size_t)i * 4] = u;
    }
}
__global__ void count_kernel(const int* __restrict__ eidx) {
    int i = blockIdx.x * blockDim.x + threadIdx.x;
    if (i < A_TOTAL) atomicAdd(&g_counts[eidx[i]], 1);
}
__global__ void scan_kernel() {
    if (threadIdx.x == 0 && blockIdx.x == 0) {
        for (int i = 0; i < MAX_MTILES; i++) g_tile_expert[i] = -1;
        int acc = 0;
        for (int e = 0; e < N_EXPERTS; e++) {
            g_offsets[e] = acc;
            int nt = (g_counts[e] + BM - 1) / BM;
            int t0 = acc / BM;
            for (int i = 0; i < nt; i++) g_tile_expert[t0 + i] = e;
            acc += nt * BM;
        }
    }
}
__global__ void scatter_kernel(const int* __restrict__ eidx,
                               const float* __restrict__ ew) {
    int i = blockIdx.x * blockDim.x + threadIdx.x;
    if (i < A_TOTAL) {
        int e = eidx[i];
        int p = atomicAdd(&g_offsets[e], 1);
        g_perm[p] = i / TOP_K;
        g_wgt[p]  = ew[i];
    }
}

// ---------------- GEMM1: H = silu(X@W1) * (X@W2) ----------------
// grid (D_FF/BN=22, 144), 256 thr. Warps 2(m) x 4(n); warp tile 64x32.
__global__ void __launch_bounds__(256)
gemm1_kernel(const float* __restrict__ w1,
             const float* __restrict__ w2) {
    const int mt = blockIdx.y;
    const int e  = g_tile_expert[mt];
    if (e < 0) return;
    const int nb   = blockIdx.x * BN;
    const int row0 = mt * BM;

    extern __shared__ float smem[];
    float* sA  = smem;                       // 2 * A_STAGE
    float* sB1 = sA  + 2 * A_STAGE;          // 2 * B_STAGE
    float* sB2 = sB1 + 2 * B_STAGE;

    const int tid  = threadIdx.x;
    const int lane = tid & 31;
    const int wid  = tid >> 5;
    const int wm   = wid >> 2;      // 0..1
    const int wn   = wid & 3;       // 0..3
    const int g    = lane >> 2;
    const int t    = lane & 3;

    // A loader: 4 tasks. q = tid + 256j -> m = q>>3 (0..127), kq = q&7
    const float* apg[4];
    int av[4];
    uint32_t dA[4];
#pragma unroll
    for (int j = 0; j < 4; j++) {
        const int q = tid + 256 * j;
        const int m = q >> 3, kq = q & 7;
        const int tok = g_perm[row0 + m];
        av[j]  = (tok >= 0);
        apg[j] = g_Xr + (size_t)(tok < 0 ? 0 : tok) * D_MODEL + kq * 4;
        dA[j]  = smem_u32(sA + m * A_STRIDE + kq * 4);
    }
    // B loader: 4 tasks per matrix. q = tid + 256j -> k = q>>5 (0..31), nq = q&31
    const float* b1g[4];
    const float* b2g[4];
    uint32_t dB1[4], dB2[4];
#pragma unroll
    for (int j = 0; j < 4; j++) {
        const int q = tid + 256 * j;
        const int k = q >> 5, nq = q & 31;
        b1g[j] = w1 + (size_t)e * D_MODEL * D_FF + (size_t)k * D_FF + nb + nq * 4;
        b2g[j] = w2 + (size_t)e * D_MODEL * D_FF + (size_t)k * D_FF + nb + nq * 4;
        dB1[j] = smem_u32(sB1 + k * B_STRIDE + nq * 4);
        dB2[j] = smem_u32(sB2 + k * B_STRIDE + nq * 4);
    }

    const int KT = D_MODEL / BK;   // 32

    auto issue = [&](int kt) {
        if (kt < KT) {
            const int s = kt & 1;
            const int kg = kt * BK;
#pragma unroll
            for (int j = 0; j < 4; j++)
                cp16_pred(dA[j] + s * A_STAGE * 4, apg[j] + kg, av[j]);
#pragma unroll
            for (int j = 0; j < 4; j++) {
                cp16(dB1[j] + s * B_STAGE * 4, b1g[j] + (size_t)kg * D_FF);
                cp16(dB2[j] + s * B_STAGE * 4, b2g[j] + (size_t)kg * D_FF);
            }
        }
        CP_COMMIT();
    };

    float accg[4][4][4] = {};
    float accv[4][4][4] = {};

    issue(0); issue(1);

    for (int kt = 0; kt < KT; kt++) {
        CP_WAIT1();
        __syncthreads();

        const int s = kt & 1;
        const float* As  = sA  + s * A_STAGE;
        const float* B1s = sB1 + s * B_STAGE;
        const float* B2s = sB2 + s * B_STAGE;

#pragma unroll
        for (int ks = 0; ks < 4; ks++) {
            const int kk = ks * 8;
            uint32_t a[4][4];
#pragma unroll
            for (int mi = 0; mi < 4; mi++) {
                const int mr = wm * 64 + mi * 16;
                a[mi][0] = __float_as_uint(As[(mr + g    ) * A_STRIDE + kk + t    ]);
                a[mi][1] = __float_as_uint(As[(mr + g + 8) * A_STRIDE + kk + t    ]);
                a[mi][2] = __float_as_uint(As[(mr + g    ) * A_STRIDE + kk + t + 4]);
                a[mi][3] = __float_as_uint(As[(mr + g + 8) * A_STRIDE + kk + t + 4]);
            }
#pragma unroll
            for (int ni = 0; ni < 4; ni++) {
                const int nc = wn * 32 + ni * 8 + g;
                uint32_t b1[2], b2[2];
                b1[0] = f2tf(B1s[(kk + t    ) * B_STRIDE + nc]);
                b1[1] = f2tf(B1s[(kk + t + 4) * B_STRIDE + nc]);
                b2[0] = f2tf(B2s[(kk + t    ) * B_STRIDE + nc]);
                b2[1] = f2tf(B2s[(kk + t + 4) * B_STRIDE + nc]);
#pragma unroll
                for (int mi = 0; mi < 4; mi++) {
                    mma8(accg[mi][ni], a[mi], b1);
                    mma8(accv[mi][ni], a[mi], b2);
                }
            }
        }
        __syncthreads();
        issue(kt + 2);
    }

    // epilogue: SwiGLU -> g_H (tf32-rounded so GEMM2 loads raw)
#pragma unroll
    for (int mi = 0; mi < 4; mi++) {
        const int r = wm * 64 + mi * 16 + g;
        const size_t h0 = (size_t)(row0 + r)     * D_FF;
        const size_t h8 = (size_t)(row0 + r + 8) * D_FF;
#pragma unroll
        for (int ni = 0; ni < 4; ni++) {
            const int c = nb + wn * 32 + ni * 8 + 2 * t;
            uint2 v0, v8;
            v0.x = f2tf(silu_f(accg[mi][ni][0]) * accv[mi][ni][0]);
            v0.y = f2tf(silu_f(accg[mi][ni][1]) * accv[mi][ni][1]);
            v8.x = f2tf(silu_f(accg[mi][ni][2]) * accv[mi][ni][2]);
            v8.y = f2tf(silu_f(accg[mi][ni][3]) * accv[mi][ni][3]);
            *(uint2*)&g_H[h0 + c] = v0;
            *(uint2*)&g_H[h8 + c] = v8;
        }
    }
}

// ---------------- GEMM2: out += wgt * (H @ W3) ----------------
// grid (D_MODEL/BN=8, 144), 256 thr, 2 CTAs/SM.
__global__ void __launch_bounds__(256, 2)
gemm2_kernel(const float* __restrict__ w3, float* __restrict__ out) {
    const int mt = blockIdx.y;
    const int e  = g_tile_expert[mt];
    if (e < 0) return;
    const int nb   = blockIdx.x * BN;
    const int row0 = mt * BM;

    extern __shared__ float smem[];
    float* sA = smem;
    float* sB = sA + 2 * A_STAGE;

    const int tid  = threadIdx.x;
    const int lane = tid & 31;
    const int wid  = tid >> 5;
    const int wm   = wid >> 2;
    const int wn   = wid & 3;
    const int g    = lane >> 2;
    const int t    = lane & 3;

    const float* apg[4];
    uint32_t dA[4];
#pragma unroll
    for (int j = 0; j < 4; j++) {
        const int q = tid + 256 * j;
        const int m = q >> 3, kq = q & 7;
        apg[j] = g_H + (size_t)(row0 + m) * D_FF + kq * 4;   // pad rows are zero
        dA[j]  = smem_u32(sA + m * A_STRIDE + kq * 4);
    }
    const float* bg[4];
    uint32_t dB[4];
#pragma unroll
    for (int j = 0; j < 4; j++) {
        const int q = tid + 256 * j;
        const int k = q >> 5, nq = q & 31;
        bg[j] = w3 + (size_t)e * D_FF * D_MODEL + (size_t)k * D_MODEL + nb + nq * 4;
        dB[j] = smem_u32(sB + k * B_STRIDE + nq * 4);
    }

    const int KT = D_FF / BK;   // 88

    auto issue = [&](int kt) {
        if (kt < KT) {
            const int s = kt & 1;
            const int kg = kt * BK;
#pragma unroll
            for (int j = 0; j < 4; j++)
                cp16(dA[j] + s * A_STAGE * 4, apg[j] + kg);
#pragma unroll
            for (int j = 0; j < 4; j++)
                cp16(dB[j] + s * B_STAGE * 4, bg[j] + (size_t)kg * D_MODEL);
        }
        CP_COMMIT();
    };

    float acc[4][4][4] = {};

    issue(0); issue(1);

    for (int kt = 0; kt < KT; kt++) {
        CP_WAIT1();
        __syncthreads();

        const int s = kt & 1;
        const float* As = sA + s * A_STAGE;
        const float* Bs = sB + s * B_STAGE;

#pragma unroll
        for (int ks = 0; ks < 4; ks++) {
            const int kk = ks * 8;
            uint32_t a[4][4];
#pragma unroll
            for (int mi = 0; mi < 4; mi++) {
                const int mr = wm * 64 + mi * 16;
                a[mi][0] = __float_as_uint(As[(mr + g    ) * A_STRIDE + kk + t    ]);
                a[mi][1] = __float_as_uint(As[(mr + g + 8) * A_STRIDE + kk + t    ]);
                a[mi][2] = __float_as_uint(As[(mr + g    ) * A_STRIDE + kk + t + 4]);
                a[mi][3] = __float_as_uint(As[(mr + g + 8) * A_STRIDE + kk + t + 4]);
            }
#pragma unroll
            for (int ni = 0; ni < 4; ni++) {
                const int nc = wn * 32 + ni * 8 + g;
                uint32_t b[2];
                b[0] = f2tf(Bs[(kk + t    ) * B_STRIDE + nc]);
                b[1] = f2tf(Bs[(kk + t + 4) * B_STRIDE + nc]);
#pragma unroll
                for (int mi = 0; mi < 4; mi++)
                    mma8(acc[mi][ni], a[mi], b);
            }
        }
        __syncthreads();
        issue(kt + 2);
    }

    // epilogue: weighted scatter-add (2 commutative adds per token -> deterministic)
#pragma unroll
    for (int mi = 0; mi < 4; mi++) {
        const int r  = wm * 64 + mi * 16 + g;
        const int s0 = row0 + r;
        const int s8 = s0 + 8;
        const int tk0 = g_perm[s0];
        const int tk8 = g_perm[s8];
        const float wt0 = (tk0 >= 0) ? g_wgt[s0] : 0.f;
        const float wt8 = (tk8 >= 0) ? g_wgt[s8] : 0.f;
#pragma unroll
        for (int ni = 0; ni < 4; ni++) {
            const int c = nb + wn * 32 + ni * 8 + 2 * t;
            if (tk0 >= 0) {
                atomicAdd(&out[(size_t)tk0 * D_MODEL + c    ], acc[mi][ni][0] * wt0);
                atomicAdd(&out[(size_t)tk0 * D_MODEL + c + 1], acc[mi][ni][1] * wt0);
            }
            if (tk8 >= 0) {
                atomicAdd(&out[(size_t)tk8 * D_MODEL + c    ], acc[mi][ni][2] * wt8);
                atomicAdd(&out[(size_t)tk8 * D_MODEL + c + 1], acc[mi][ni][3] * wt8);
            }
        }
    }
}

// ---------------- launch ----------------
extern "C" void kernel_launch(void* const* d_in, const int* in_sizes, int n_in,
                              void* d_out, int out_size) {
    const float* x    = (const float*)d_in[0];
    const int*   eidx = (const int*)  d_in[1];
    const float* ew   = (const float*)d_in[2];
    const float* w1   = (const float*)d_in[3];
    const float* w2   = (const float*)d_in[4];
    const float* w3   = (const float*)d_in[5];
    float* out = (float*)d_out;

    const int smem1 = 2 * (A_STAGE + 2 * B_STAGE) * 4;   // 106496 B
    const int smem2 = 2 * (A_STAGE + B_STAGE) * 4;       //  71680 B
    static int attr_done = 0;
    if (!attr_done) {
        cudaFuncSetAttribute(gemm1_kernel, cudaFuncAttributeMaxDynamicSharedMemorySize, smem1);
        cudaFuncSetAttribute(gemm2_kernel, cudaFuncAttributeMaxDynamicSharedMemorySize, smem2);
        attr_done = 1;
    }

    init_kernel<<<(MAX_SLOTS + 255) / 256, 256>>>();
    zero_out_kernel<<<(N_TOKENS * D_MODEL / 4 + 255) / 256, 256>>>((float4*)out);
    round_x_kernel<<<(N_TOKENS * D_MODEL / 4 + 255) / 256, 256>>>((const float4*)x);
    count_kernel<<<(A_TOTAL + 255) / 256, 256>>>(eidx);
    scan_kernel<<<1, 32>>>();
    scatter_kernel<<<(A_TOTAL + 255) / 256, 256>>>(eidx, ew);

    gemm1_kernel<<<dim3(D_FF / BN, MAX_MTILES), 256, smem1>>>(w1, w2);
    gemm2_kernel<<<dim3(D_MODEL / BN, MAX_MTILES), 256, smem2>>>(w3, out);
}